// round 17
// baseline (speedup 1.0000x reference)
#include <cuda_runtime.h>
#include <cuda_fp16.h>
#include <stdint.h>

// HybridMixSTEDecoder: 5 disjoint-group GEMMs (27648x512 @ 512xN_i) + bias,
// scattered into out[b, tp*9+p, joint, c]. Groups disjoint -> count/div identity.
//
// Single-pass fp16 mma.sync (A, B RN-rounded fp16, fp32 accum; rel_err ~3e-4).
// L1tex-wavefront-minimized variant: 32 M-rows per warp (B ldmatrix shared by
// two 16-row fragments -> B wf/row halves) with N split into 48-col slices
// (11 variants) so accumulators fit registers. K-chunk 32, register A buffer,
// line-packed B tiles via cp.async double buffer. 128-thr CTAs, 4/SM.

// 11 variants x 48 padded rows x 512 fp16 = 135168 u32.
// v 0..7: groups {0,1,3,4} x col-halves {0,48}; v 8..10: g2 col-thirds.
static __device__ __align__(16) uint32_t g_B[11 * 12288];

// ---------------- helpers ----------------
static __device__ __forceinline__ uint32_t s2u(const void* p) {
    uint32_t a;
    asm("{ .reg .u64 t; cvta.to.shared.u64 t, %1; cvt.u32.u64 %0, t; }"
        : "=r"(a) : "l"(p));
    return a;
}
static __device__ __forceinline__ uint32_t f16x2_rn(float lo, float hi) {
    uint32_t r; asm("cvt.rn.f16x2.f32 %0, %1, %2;" : "=r"(r) : "f"(hi), "f"(lo));
    return r;  // low half = lo, high half = hi
}
static __device__ __forceinline__ void ldsm_x4(uint32_t* r, uint32_t addr) {
    asm volatile("ldmatrix.sync.aligned.m8n8.x4.shared.b16 {%0,%1,%2,%3}, [%4];"
        : "=r"(r[0]), "=r"(r[1]), "=r"(r[2]), "=r"(r[3]) : "r"(addr));
}
static __device__ __forceinline__ void mma_f16(float* d, const uint32_t* a,
                                               const uint32_t* b) {
    asm volatile(
        "mma.sync.aligned.m16n8k16.row.col.f32.f16.f16.f32 "
        "{%0,%1,%2,%3}, {%4,%5,%6,%7}, {%8,%9}, {%0,%1,%2,%3};"
        : "+f"(d[0]), "+f"(d[1]), "+f"(d[2]), "+f"(d[3])
        : "r"(a[0]), "r"(a[1]), "r"(a[2]), "r"(a[3]), "r"(b[0]), "r"(b[1]));
}
static __device__ __forceinline__ void cp16(uint32_t dst, const void* src, int pred) {
    asm volatile(
        "{\n\t.reg .pred p;\n\tsetp.ne.b32 p, %0, 0;\n\t"
        "@p cp.async.cg.shared.global [%1], [%2], 16;\n\t}"
        :: "r"(pred), "r"(dst), "l"(src));
}

// ---------------- prep: W (f32) -> fp16 tile-packed per chunk32 -------------
// k-permute (matches A fragment): raw (k,k+1) -> eff (2t,2t+1) in ku=0 tile,
// raw (k+2,k+3) -> eff (2t+8,2t+9) in ku=1 tile; t=(k>>2)&3, jj=(k>>4)&1,
// kc=k>>5. Stage layout per kc: line = ntile*4 + jj*2 + ku (24 lines x 128B).
__global__ void __launch_bounds__(256) prep_B(
    const float* __restrict__ W0, const float* __restrict__ W1,
    const float* __restrict__ W2, const float* __restrict__ W3,
    const float* __restrict__ W4)
{
    int idx = blockIdx.x * 256 + threadIdx.x;   // one thread per (grow, k4)
    if (idx >= 528 * 128) return;
    int grow = idx >> 7;
    int k = (idx & 127) << 2;
    int v = grow / 48;
    int n = grow - v * 48;

    const float* Wg;
    int CO, N;
    if (v < 8) {
        int gsel = v >> 1;
        Wg = (gsel == 0) ? W0 : (gsel == 1) ? W1 : (gsel == 2) ? W3 : W4;
        CO = (v & 1) * 48;
        N = 81;
    } else {
        Wg = W2;
        CO = (v - 8) * 48;
        N = 135;
    }
    int n_src = CO + n;

    float4 w = make_float4(0.f, 0.f, 0.f, 0.f);
    if (n_src < N) w = *(const float4*)(Wg + n_src * 512 + k);

    uint32_t h01 = f16x2_rn(w.x, w.y);
    uint32_t h23 = f16x2_rn(w.z, w.w);

    int kc = k >> 5, jj = (k >> 4) & 1, t = (k >> 2) & 3;
    uint32_t* dst = g_B + v * 12288 + kc * 768
                  + ((n >> 3) * 4 + jj * 2) * 32 + (n & 7) * 4 + t;
    dst[0]  = h01;   // ku = 0
    dst[32] = h23;   // ku = 1
}

// ---------------- fused core ----------------
// Smem: two B stages of 3072 B (24 tile-lines x 128B), contiguous from g_B.
template<int GS>
static __device__ __forceinline__ void decode_core(
    const float* __restrict__ tokens,
    const uint32_t* __restrict__ Breg,     // variant base in g_B
    const float* __restrict__ bias,
    float* __restrict__ out,
    int gidx, int jb3, int CO)
{
    constexpr int NT    = 6;
    constexpr int NREAL = (GS == 5) ? 135 : 81;
    constexpr int BBS   = 3072;            // B stage bytes (one chunk32)

    __shared__ __align__(16) char smem[2 * BBS];
    const uint32_t su = s2u(smem);

    const int tid  = threadIdx.x;
    const int wid  = tid >> 5;             // 0..3
    const int lane = tid & 31;

    const int m0 = blockIdx.y * 128;

    // A direct-load (k-permuted): lane (r = lane>>2, tig = lane&3) loads
    // float4 at (row 32*wid + r + 8*rg, k = 32*kc + 16*jj + 4*tig).
    const float* aw = tokens
        + (size_t)(m0 + 32 * wid + (lane >> 2)) * 2560
        + gidx * 512 + (lane & 3) * 4;

    // B ldmatrix lane addressing (line-packed; x4 covers 2 n-tiles x 2 ku):
    const uint32_t bl = (uint32_t)((((lane >> 4) & 1) << 9)
                      + (((lane >> 3) & 1) << 7) + ((lane & 7) << 4));

    float acc[2][NT][4];
    #pragma unroll
    for (int f = 0; f < 2; f++)
        #pragma unroll
        for (int t = 0; t < NT; t++)
            #pragma unroll
            for (int q = 0; q < 4; q++) acc[f][t][q] = 0.f;

    // Full-chunk A register buffer: ra[jj*4 + rg], rg = row-group (r+8*rg).
    float4 ra[8];
    #pragma unroll
    for (int jj = 0; jj < 2; jj++)
        #pragma unroll
        for (int rg = 0; rg < 4; rg++)
            ra[jj * 4 + rg] = *(const float4*)(aw + jj * 16 + rg * 20480);

    // B(0) cp.async (contiguous; layout pre-baked in prep_B)
    {
        const char* bsrc = (const char*)Breg;
        #pragma unroll
        for (int it = 0; it < 2; it++) {
            int i2 = tid + it * 128;
            cp16(su + (uint32_t)(i2 * 16), bsrc + i2 * 16, i2 < 192);
        }
        asm volatile("cp.async.commit_group;" ::: "memory");
    }

    #pragma unroll 1
    for (int kc = 0; kc < 16; kc++) {
        const int s = kc & 1;

        asm volatile("cp.async.wait_group 0;" ::: "memory");
        __syncthreads();
        if (kc < 15) {
            const uint32_t bdst = su + (uint32_t)((s ^ 1) * BBS);
            const char* bsrc = (const char*)(Breg + (kc + 1) * 768);
            #pragma unroll
            for (int it = 0; it < 2; it++) {
                int i2 = tid + it * 128;
                cp16(bdst + (uint32_t)(i2 * 16), bsrc + i2 * 16, i2 < 192);
            }
            asm volatile("cp.async.commit_group;" ::: "memory");
        }

        const uint32_t bBase = su + (uint32_t)(s * BBS);
        #pragma unroll
        for (int jj = 0; jj < 2; jj++) {
            // two A fragments (rows r/r+8 and r+16/r+24) from reg buffer
            uint32_t a0[4], a1[4];
            a0[0] = f16x2_rn(ra[jj * 4 + 0].x, ra[jj * 4 + 0].y);
            a0[2] = f16x2_rn(ra[jj * 4 + 0].z, ra[jj * 4 + 0].w);
            a0[1] = f16x2_rn(ra[jj * 4 + 1].x, ra[jj * 4 + 1].y);
            a0[3] = f16x2_rn(ra[jj * 4 + 1].z, ra[jj * 4 + 1].w);
            a1[0] = f16x2_rn(ra[jj * 4 + 2].x, ra[jj * 4 + 2].y);
            a1[2] = f16x2_rn(ra[jj * 4 + 2].z, ra[jj * 4 + 2].w);
            a1[1] = f16x2_rn(ra[jj * 4 + 3].x, ra[jj * 4 + 3].y);
            a1[3] = f16x2_rn(ra[jj * 4 + 3].z, ra[jj * 4 + 3].w);
            // refill these slots from chunk kc+1 (lookahead = one chunk)
            if (kc < 15) {
                const float* ap = aw + (kc + 1) * 32 + jj * 16;
                #pragma unroll
                for (int rg = 0; rg < 4; rg++)
                    ra[jj * 4 + rg] = *(const float4*)(ap + rg * 20480);
            }
            // B tiles + MMAs (each B fragment feeds BOTH A fragments)
            const uint32_t bj = bBase + (uint32_t)(jj * 256);
            #pragma unroll
            for (int q = 0; q < 3; q++) {
                uint32_t bh[4];
                ldsm_x4(bh, bj + (uint32_t)(q * 1024) + bl);
                mma_f16(acc[0][2 * q],     a0, bh);
                mma_f16(acc[0][2 * q + 1], a0, bh + 2);
                mma_f16(acc[1][2 * q],     a1, bh);
                mma_f16(acc[1][2 * q + 1], a1, bh + 2);
            }
        }
    }

    // ---- epilogue: bias + scatter ----
    const int g   = lane >> 2;
    const int tig = lane & 3;

    int   coff[NT][2];
    float cb[NT][2];
    #pragma unroll
    for (int t = 0; t < NT; t++) {
        #pragma unroll
        for (int h = 0; h < 2; h++) {
            int o = CO + 8 * t + 2 * tig + h;
            if (o < NREAL) {
                int p   = o / (GS * 3);
                int rem = o - p * (GS * 3);
                int joff = (GS == 5) ? ((rem < 3) ? rem : rem + 18) : (jb3 + rem);
                coff[t][h] = p * 51 + joff;
                cb[t][h]   = bias[o];
            } else {
                coff[t][h] = -1;
                cb[t][h]   = 0.f;
            }
        }
    }

    #pragma unroll
    for (int f = 0; f < 2; f++) {
        #pragma unroll
        for (int half = 0; half < 2; half++) {
            int m  = m0 + 32 * wid + 16 * f + g + 8 * half;
            int b  = m / 27;
            int tp = m - b * 27;
            size_t obase = (size_t)b * 12393 + (size_t)tp * 459;
            #pragma unroll
            for (int t = 0; t < NT; t++) {
                float v0 = acc[f][t][2 * half];
                float v1 = acc[f][t][2 * half + 1];
                if (coff[t][0] >= 0) out[obase + coff[t][0]] = v0 + cb[t][0];
                if (coff[t][1] >= 0) out[obase + coff[t][1]] = v1 + cb[t][1];
            }
        }
    }
}

// blockIdx.x = variant (0..10), blockIdx.y = m-block of 128 rows (same token
// rows across all variants -> L2 reuse; output rows merge in L2).
__global__ void __launch_bounds__(128, 4) dec_all(
    const float* __restrict__ tokens,
    const float* __restrict__ b0, const float* __restrict__ b1,
    const float* __restrict__ b2, const float* __restrict__ b3,
    const float* __restrict__ b4,
    float* __restrict__ out)
{
    int y = blockIdx.x;
    if (y < 8) {
        int gsel = y >> 1;
        int gidx, jb3;
        const float* bias;
        switch (gsel) {
            case 0:  gidx = 0; jb3 = 3;  bias = b0; break;
            case 1:  gidx = 1; jb3 = 12; bias = b1; break;
            case 2:  gidx = 3; jb3 = 33; bias = b3; break;
            default: gidx = 4; jb3 = 42; bias = b4; break;
        }
        decode_core<3>(tokens, g_B + y * 12288, bias, out, gidx, jb3,
                       (y & 1) * 48);
    } else {
        decode_core<5>(tokens, g_B + y * 12288, b2, out, 2, 0,
                       (y - 8) * 48);
    }
}

extern "C" void kernel_launch(void* const* d_in, const int* in_sizes, int n_in,
                              void* d_out, int out_size) {
    const float* tokens = (const float*)d_in[0];
    const float* W[5];
    const float* B[5];
    for (int i = 0; i < 5; i++) {
        W[i] = (const float*)d_in[1 + 2 * i];
        B[i] = (const float*)d_in[2 + 2 * i];
    }
    float* out = (float*)d_out;

    prep_B<<<(528 * 128 + 255) / 256, 256>>>(W[0], W[1], W[2], W[3], W[4]);
    dec_all<<<dim3(11, 216), 128>>>(tokens, B[0], B[1], B[2], B[3], B[4], out);
}